// round 13
// baseline (speedup 1.0000x reference)
#include <cuda_runtime.h>
#include <cuda_fp16.h>
#include <math.h>

// Problem dims (fixed by the dataset)
#define NN 4
#define HH 512
#define WW 512
#define CC 64

#define CPB     64                 // channels per tile = full row
#define THREADS 512
#define ROWLEN  512
#define NCHUNK  16                 // one warp per chunk; lane = half2 channel pair
#define CLEN    (ROWLEN / NCHUNK)  // 32
#define LWARM   16                 // warm-up: err ~ 0.5^17 ~ 8e-6
#define H2PW    (CPB / 2)          // half2 per scan-site = 32
#define VECH    (ROWLEN * CPB / 8) // uint4 (8 halves) per fp16 tile = 4096
#define SMEM_BYTES (ROWLEN * CPB * 2) // 65536 (fp16 tile -> 3 CTAs/SM)

#define ZCOL    (HH * CC)          // elements per z column blob = 32768

// ---- Blackwell packed f32x2 helpers (PTX-only; ptxas won't auto-fuse) ----
union f2u64 { float2 f; unsigned long long u; };

__device__ __forceinline__ float2 fma2(float2 a, float2 b, float2 c) {
    f2u64 A, B, C, D;
    A.f = a; B.f = b; C.f = c;
    asm("fma.rn.f32x2 %0, %1, %2, %3;" : "=l"(D.u) : "l"(A.u), "l"(B.u), "l"(C.u));
    return D.f;
}
__device__ __forceinline__ float2 mul2(float2 a, float2 b) {
    f2u64 A, B, D;
    A.f = a; B.f = b;
    asm("mul.rn.f32x2 %0, %1, %2;" : "=l"(D.u) : "l"(A.u), "l"(B.u));
    return D.f;
}

// W-filtered image, fp16, W-MAJOR layout: z[n][w][h][c].
__device__ __half g_scratch[(size_t)NN * HH * WW * CC];

// Fwd+bwd IIR (a=b=0.5) over a ROWLEN x CC half2 tile in smem, in place.
// Dual fp32 carry chains packed in one f32x2 chain (1 fma2/step dependent).
// Boundary chunks exact w.r.t. reference inits.
__device__ __forceinline__ void iir_scan_tile_h2(__half2* s, int tid) {
    const int c     = tid & 31;
    const int chunk = tid >> 5;
    const int w0    = chunk * CLEN;
    const int w1    = w0 + CLEN;
    const float2 HF = make_float2(0.5f, 0.5f);

    int ws = w0 - LWARM; if (ws < 0) ws = 0;
    float2 carry = __half22float2(s[ws * H2PW + c]);
    for (int w = ws; w < w0; ++w)
        carry = fma2(HF, carry, mul2(HF, __half22float2(s[w * H2PW + c])));
    __syncthreads();

    #pragma unroll
    for (int w = w0; w < w1; ++w) {
        carry = fma2(HF, carry, mul2(HF, __half22float2(s[w * H2PW + c])));
        s[w * H2PW + c] = __floats2half2_rn(carry.x, carry.y);
    }
    __syncthreads();

    int we = w1 - 1 + LWARM; if (we > ROWLEN - 1) we = ROWLEN - 1;
    carry = __half22float2(s[we * H2PW + c]);
    for (int w = we - 1; w >= w1; --w)
        carry = fma2(HF, carry, mul2(HF, __half22float2(s[w * H2PW + c])));
    __syncthreads();

    #pragma unroll
    for (int w = w1 - 1; w >= w0; --w) {
        carry = fma2(HF, carry, mul2(HF, __half22float2(s[w * H2PW + c])));
        s[w * H2PW + c] = __floats2half2_rn(carry.x, carry.y);
    }
    __syncthreads();
}

// Pass 1: IIR along W over row (n,h). Reads x (NHWC fp32), writes z w-major.
__global__ void __launch_bounds__(THREADS, 3)
pass1_kernel(const float* __restrict__ x) {
    extern __shared__ __half2 s2[];
    uint4* s4 = reinterpret_cast<uint4*>(s2);

    const int    nh    = blockIdx.x;                // n*HH + h
    const int    n     = nh >> 9;
    const int    h     = nh & 511;
    const size_t xbase = (size_t)nh * (WW * CC);
    const size_t zbase = ((size_t)n * WW) * ZCOL + (size_t)h * CC;

    #pragma unroll
    for (int i = threadIdx.x; i < VECH; i += THREADS) {
        const int w = i >> 3;
        const int q = i & 7;
        const float4 a = *(const float4*)(x + xbase + (size_t)w * CC + q * 8);
        const float4 b = *(const float4*)(x + xbase + (size_t)w * CC + q * 8 + 4);
        __half2 hv[4];
        hv[0] = __floats2half2_rn(a.x, a.y);
        hv[1] = __floats2half2_rn(a.z, a.w);
        hv[2] = __floats2half2_rn(b.x, b.y);
        hv[3] = __floats2half2_rn(b.z, b.w);
        s4[w * 8 + q] = *(uint4*)hv;
    }
    __syncthreads();

    iir_scan_tile_h2(s2, threadIdx.x);

    // z[n][w][h][c]: per w a full 128B line (8 uint4), stride 64KB in w.
    #pragma unroll
    for (int i = threadIdx.x; i < VECH; i += THREADS) {
        const int w = i >> 3;
        const int q = i & 7;
        *(uint4*)(g_scratch + zbase + (size_t)w * ZCOL + q * 8) = s4[w * 8 + q];
    }
}

// Pass 2: IIR along H over column (n,w); reconstruct x from z[w-1,w,w+1]
// (exact filter inverse) and write the residual mix. Never reads fp32 x.
__global__ void __launch_bounds__(THREADS, 3)
pass2_kernel(const float* __restrict__ alpha,
             float*       __restrict__ out) {
    extern __shared__ __half2 s2[];
    uint4* s4 = reinterpret_cast<uint4*>(s2);
    __shared__ __align__(16) float sm[CPB];   // mix = sigmoid(alpha)
    __shared__ __align__(16) float so[CPB];   // 1 - mix

    const int    nw    = blockIdx.x;                // n*WW + w
    const int    n     = nw >> 9;
    const int    w     = nw & 511;
    const size_t zbase = ((size_t)n * WW + w) * ZCOL;
    const size_t obase = (size_t)n * (HH * WW * CC) + (size_t)w * CC;

    if (threadIdx.x < CPB) {
        const float m = 1.0f / (1.0f + expf(-alpha[threadIdx.x]));
        sm[threadIdx.x] = m;
        so[threadIdx.x] = 1.0f - m;
    }

    // z column blob: contiguous 64KB copy into smem ([h][c] tile).
    const uint4* zc = (const uint4*)(g_scratch + zbase);
    #pragma unroll
    for (int i = threadIdx.x; i < VECH; i += THREADS)
        s4[i] = zc[i];
    __syncthreads();

    iir_scan_tile_h2(s2, threadIdx.x);

    // Exact inverse of the W filter:
    //   w in [1,510]: x = 5 z[w] - 2 z[w-1] - 2 z[w+1]
    //   w = 0:        x = 2 z[0] - z[1]
    //   w = 511:      x = 3 z[511] - 2 z[510]
    float cm, c0, cp;
    const __half *zm, *zp;
    if (w == 0)        { cm = 0.f;  c0 = 2.f; cp = -1.f;
                         zm = g_scratch + zbase; zp = g_scratch + zbase + ZCOL; }
    else if (w == 511) { cm = -2.f; c0 = 3.f; cp = 0.f;
                         zm = g_scratch + zbase - ZCOL; zp = g_scratch + zbase; }
    else               { cm = -2.f; c0 = 5.f; cp = -2.f;
                         zm = g_scratch + zbase - ZCOL; zp = g_scratch + zbase + ZCOL; }
    const __half* z0 = g_scratch + zbase;   // re-read own column (L2-hot)
    const float2 c02 = make_float2(c0, c0);
    const float2 cm2 = make_float2(cm, cm);
    const float2 cp2 = make_float2(cp, cp);

    // Epilogue: per i -> (h, q) = 8 channels; 3x 16B z (L2-hot) + 16B y
    // (smem) in, 32B out. Independent iterations, packed f32x2 math.
    #pragma unroll
    for (int i = threadIdx.x; i < VECH; i += THREADS) {
        const int    h  = i >> 3;
        const int    q  = i & 7;
        const size_t zo = (size_t)h * CC + q * 8;
        const uint4  u0 = *(const uint4*)(z0 + zo);
        const uint4  um = *(const uint4*)(zm + zo);
        const uint4  up = *(const uint4*)(zp + zo);
        const __half2* h0 = (const __half2*)&u0;
        const __half2* hm = (const __half2*)&um;
        const __half2* hp = (const __half2*)&up;
        const __half2* hy = s2 + h * H2PW + q * 4;

        float outv[8];
        #pragma unroll
        for (int k = 0; k < 4; ++k) {
            const float2 v0 = __half22float2(h0[k]);
            const float2 vm = __half22float2(hm[k]);
            const float2 vp = __half22float2(hp[k]);
            const float2 yv = __half22float2(hy[k]);
            const float2 mv = *(const float2*)(&sm[q * 8 + k * 2]);
            const float2 ov = *(const float2*)(&so[q * 8 + k * 2]);
            // x_hat = c0*z0 + cm*zm + cp*zp ; out = mix*y + (1-mix)*x_hat
            const float2 xh = fma2(c02, v0, fma2(cm2, vm, mul2(cp2, vp)));
            const float2 o  = fma2(mv, yv, mul2(ov, xh));
            outv[2 * k]     = o.x;
            outv[2 * k + 1] = o.y;
        }
        float* op = out + obase + (size_t)h * (WW * CC) + q * 8;
        *(float4*)op       = *(float4*)&outv[0];
        *(float4*)(op + 4) = *(float4*)&outv[4];
    }
}

extern "C" void kernel_launch(void* const* d_in, const int* in_sizes, int n_in,
                              void* d_out, int out_size) {
    const float* x     = (const float*)d_in[0];
    const float* alpha = (const float*)d_in[1];
    float*       out   = (float*)d_out;

    // >48KB dynamic smem opt-in (idempotent, capture-safe).
    cudaFuncSetAttribute(pass1_kernel,
                         cudaFuncAttributeMaxDynamicSharedMemorySize, SMEM_BYTES);
    cudaFuncSetAttribute(pass2_kernel,
                         cudaFuncAttributeMaxDynamicSharedMemorySize, SMEM_BYTES);

    pass1_kernel<<<NN * HH, THREADS, SMEM_BYTES>>>(x);
    pass2_kernel<<<NN * WW, THREADS, SMEM_BYTES>>>(alpha, out);
}

// round 14
// speedup vs baseline: 1.2284x; 1.2284x over previous
#include <cuda_runtime.h>
#include <cuda_fp16.h>
#include <math.h>

// Problem dims (fixed by the dataset)
#define NN 4
#define HH 512
#define WW 512
#define CC 64

#define CPB     64                 // channels per tile = full row
#define THREADS 512
#define ROWLEN  512
#define NCHUNK  16                 // one warp per chunk; lane = half2 channel pair
#define CLEN    (ROWLEN / NCHUNK)  // 32
#define LWARM   16                 // warm-up: err ~ 0.5^17 ~ 8e-6
#define H2PW    (CPB / 2)          // half2 per scan-site = 32
#define VECH    (ROWLEN * CPB / 8) // uint4 (8 halves) per fp16 tile = 4096
#define SMEM_BYTES (ROWLEN * CPB * 2) // 65536 (fp16 tile -> 3 CTAs/SM)

#define ZCOL    (HH * CC)          // elements per z column blob = 32768

// W-filtered image, fp16, W-MAJOR layout: z[n][w][h][c].
__device__ __half g_scratch[(size_t)NN * HH * WW * CC];

// Pass 1: IIR along W over row (n,h). Forward warm-up/scan consume x (fp32)
// STRAIGHT from gmem (no smem copy-in; full-precision forward input),
// writing y_f fp16 to smem. Backward phases operate on smem; final store
// streams the tile to the w-major z scratch.
__global__ void __launch_bounds__(THREADS, 3)
pass1_kernel(const float* __restrict__ x) {
    extern __shared__ __half2 s2[];
    uint4* s4 = reinterpret_cast<uint4*>(s2);

    const int    nh    = blockIdx.x;                // n*HH + h
    const int    n     = nh >> 9;
    const int    h     = nh & 511;
    const float* xr    = x + (size_t)nh * (WW * CC);
    const size_t zbase = ((size_t)n * WW) * ZCOL + (size_t)h * CC;

    const int c2    = threadIdx.x & 31;
    const int chunk = threadIdx.x >> 5;
    const int w0    = chunk * CLEN;
    const int w1    = w0 + CLEN;

    // ---- forward warm-up: gmem fp32 reads (L1/L2-hot; chunk 0 exact) ----
    int ws = w0 - LWARM; if (ws < 0) ws = 0;
    float2 carry = *(const float2*)(xr + (size_t)ws * CC + c2 * 2);
    for (int w = ws; w < w0; ++w) {
        const float2 v = *(const float2*)(xr + (size_t)w * CC + c2 * 2);
        carry.x = fmaf(0.5f, carry.x, 0.5f * v.x);
        carry.y = fmaf(0.5f, carry.y, 0.5f * v.y);
    }
    // No barrier: smem untouched so far.

    // ---- forward scan: gmem fp32 in, smem fp16 y_f out ----
    #pragma unroll 8
    for (int w = w0; w < w1; ++w) {
        const float2 v = *(const float2*)(xr + (size_t)w * CC + c2 * 2);
        carry.x = fmaf(0.5f, carry.x, 0.5f * v.x);
        carry.y = fmaf(0.5f, carry.y, 0.5f * v.y);
        s2[w * H2PW + c2] = __floats2half2_rn(carry.x, carry.y);
    }
    __syncthreads();

    // ---- backward warm-up (smem y_f, next chunk's region) ----
    int we = w1 - 1 + LWARM; if (we > ROWLEN - 1) we = ROWLEN - 1;
    carry = __half22float2(s2[we * H2PW + c2]);
    for (int w = we - 1; w >= w1; --w) {
        const float2 v = __half22float2(s2[w * H2PW + c2]);
        carry.x = fmaf(0.5f, carry.x, 0.5f * v.x);
        carry.y = fmaf(0.5f, carry.y, 0.5f * v.y);
    }
    __syncthreads();   // warm-up reads of neighbor regions must finish first

    // ---- backward scan, in place ----
    #pragma unroll
    for (int w = w1 - 1; w >= w0; --w) {
        const float2 v = __half22float2(s2[w * H2PW + c2]);
        carry.x = fmaf(0.5f, carry.x, 0.5f * v.x);
        carry.y = fmaf(0.5f, carry.y, 0.5f * v.y);
        s2[w * H2PW + c2] = __floats2half2_rn(carry.x, carry.y);
    }
    __syncthreads();

    // ---- store: z[n][w][h][c], per w a full 128B line, stride 64KB ----
    #pragma unroll
    for (int i = threadIdx.x; i < VECH; i += THREADS) {
        const int w = i >> 3;
        const int q = i & 7;
        *(uint4*)(g_scratch + zbase + (size_t)w * ZCOL + q * 8) = s4[w * 8 + q];
    }
}

// Pass 2: IIR along H over column (n,w). Forward warm-up/scan consume the
// contiguous z blob straight from gmem (fp16), writing y_f to smem; then
// backward in smem; epilogue reconstructs x from z[w-1,w,w+1] (exact filter
// inverse, L2-hot) and writes the residual mix. Never reads fp32 x.
__global__ void __launch_bounds__(THREADS, 3)
pass2_kernel(const float* __restrict__ alpha,
             float*       __restrict__ out) {
    extern __shared__ __half2 s2[];
    __shared__ __align__(16) float sm[CPB];

    const int    nw    = blockIdx.x;                // n*WW + w
    const int    n     = nw >> 9;
    const int    w     = nw & 511;
    const size_t zbase = ((size_t)n * WW + w) * ZCOL;
    const size_t obase = (size_t)n * (HH * WW * CC) + (size_t)w * CC;
    const __half* z0   = g_scratch + zbase;

    if (threadIdx.x < CPB)
        sm[threadIdx.x] = 1.0f / (1.0f + expf(-alpha[threadIdx.x]));

    const int c2    = threadIdx.x & 31;
    const int chunk = threadIdx.x >> 5;
    const int h0    = chunk * CLEN;
    const int h1    = h0 + CLEN;

    // ---- forward warm-up: gmem fp16 reads from the z blob ----
    int hs = h0 - LWARM; if (hs < 0) hs = 0;
    float2 carry = __half22float2(*(const __half2*)(z0 + (size_t)hs * CC + c2 * 2));
    for (int h = hs; h < h0; ++h) {
        const float2 v = __half22float2(*(const __half2*)(z0 + (size_t)h * CC + c2 * 2));
        carry.x = fmaf(0.5f, carry.x, 0.5f * v.x);
        carry.y = fmaf(0.5f, carry.y, 0.5f * v.y);
    }
    // No barrier: smem untouched so far (sm[] written pre-scan, read post-sync).

    // ---- forward scan: gmem fp16 in, smem fp16 y_f out ----
    #pragma unroll 8
    for (int h = h0; h < h1; ++h) {
        const float2 v = __half22float2(*(const __half2*)(z0 + (size_t)h * CC + c2 * 2));
        carry.x = fmaf(0.5f, carry.x, 0.5f * v.x);
        carry.y = fmaf(0.5f, carry.y, 0.5f * v.y);
        s2[h * H2PW + c2] = __floats2half2_rn(carry.x, carry.y);
    }
    __syncthreads();

    // ---- backward warm-up (smem y_f) ----
    int he = h1 - 1 + LWARM; if (he > ROWLEN - 1) he = ROWLEN - 1;
    carry = __half22float2(s2[he * H2PW + c2]);
    for (int h = he - 1; h >= h1; --h) {
        const float2 v = __half22float2(s2[h * H2PW + c2]);
        carry.x = fmaf(0.5f, carry.x, 0.5f * v.x);
        carry.y = fmaf(0.5f, carry.y, 0.5f * v.y);
    }
    __syncthreads();

    // ---- backward scan, in place ----
    #pragma unroll
    for (int h = h1 - 1; h >= h0; --h) {
        const float2 v = __half22float2(s2[h * H2PW + c2]);
        carry.x = fmaf(0.5f, carry.x, 0.5f * v.x);
        carry.y = fmaf(0.5f, carry.y, 0.5f * v.y);
        s2[h * H2PW + c2] = __floats2half2_rn(carry.x, carry.y);
    }
    __syncthreads();

    // Exact inverse of the W filter:
    //   w in [1,510]: x = 5 z[w] - 2 z[w-1] - 2 z[w+1]
    //   w = 0:        x = 2 z[0] - z[1]
    //   w = 511:      x = 3 z[511] - 2 z[510]
    float cm, c0, cp;
    const __half *zm, *zp;
    if (w == 0)        { cm = 0.f;  c0 = 2.f; cp = -1.f;
                         zm = z0;          zp = z0 + ZCOL; }
    else if (w == 511) { cm = -2.f; c0 = 3.f; cp = 0.f;
                         zm = z0 - ZCOL;   zp = z0; }
    else               { cm = -2.f; c0 = 5.f; cp = -2.f;
                         zm = z0 - ZCOL;   zp = z0 + ZCOL; }

    // Epilogue: per i -> (h, q) = 8 channels; 3x 16B z (L2-hot) + 16B y
    // (smem) in, 32B out. Independent iterations, full MLP.
    #pragma unroll
    for (int i = threadIdx.x; i < VECH; i += THREADS) {
        const int    h  = i >> 3;
        const int    q  = i & 7;
        const size_t zo = (size_t)h * CC + q * 8;
        const uint4  u0 = *(const uint4*)(z0 + zo);
        const uint4  um = *(const uint4*)(zm + zo);
        const uint4  up = *(const uint4*)(zp + zo);
        const __half2* hz0 = (const __half2*)&u0;
        const __half2* hzm = (const __half2*)&um;
        const __half2* hzp = (const __half2*)&up;
        const __half2* hy  = s2 + h * H2PW + q * 4;

        float outv[8];
        #pragma unroll
        for (int k = 0; k < 4; ++k) {
            const float2 v0 = __half22float2(hz0[k]);
            const float2 vm = __half22float2(hzm[k]);
            const float2 vp = __half22float2(hzp[k]);
            const float2 yv = __half22float2(hy[k]);
            const float2 mv = *(const float2*)(&sm[q * 8 + k * 2]);
            float xr, xi;
            xr = fmaf(c0, v0.x, fmaf(cm, vm.x, cp * vp.x));
            xi = fmaf(c0, v0.y, fmaf(cm, vm.y, cp * vp.y));
            outv[2 * k]     = fmaf(mv.x, yv.x - xr, xr);
            outv[2 * k + 1] = fmaf(mv.y, yv.y - xi, xi);
        }
        float* op = out + obase + (size_t)h * (WW * CC) + q * 8;
        *(float4*)op       = *(float4*)&outv[0];
        *(float4*)(op + 4) = *(float4*)&outv[4];
    }
}

extern "C" void kernel_launch(void* const* d_in, const int* in_sizes, int n_in,
                              void* d_out, int out_size) {
    const float* x     = (const float*)d_in[0];
    const float* alpha = (const float*)d_in[1];
    float*       out   = (float*)d_out;

    // >48KB dynamic smem opt-in (idempotent, capture-safe).
    cudaFuncSetAttribute(pass1_kernel,
                         cudaFuncAttributeMaxDynamicSharedMemorySize, SMEM_BYTES);
    cudaFuncSetAttribute(pass2_kernel,
                         cudaFuncAttributeMaxDynamicSharedMemorySize, SMEM_BYTES);

    pass1_kernel<<<NN * HH, THREADS, SMEM_BYTES>>>(x);
    pass2_kernel<<<NN * WW, THREADS, SMEM_BYTES>>>(alpha, out);
}

// round 15
// speedup vs baseline: 1.2667x; 1.0312x over previous
#include <cuda_runtime.h>
#include <cuda_fp16.h>
#include <math.h>

// Problem dims (fixed by the dataset)
#define NN 4
#define HH 512
#define WW 512
#define CC 64

#define CPB     64                 // channels per tile = full row
#define THREADS 512
#define ROWLEN  512
#define NCHUNK  16                 // one warp per chunk; lane = half2 channel pair
#define CLEN    (ROWLEN / NCHUNK)  // 32
#define LWARM   16                 // warm-up: err ~ 0.5^17 ~ 8e-6
#define H2PW    (CPB / 2)          // half2 per scan-site = 32
#define VECH    (ROWLEN * CPB / 8) // uint4 (8 halves) per fp16 tile = 4096
#define SMEM_BYTES (ROWLEN * CPB * 2) // 65536 (fp16 tile -> 3 CTAs/SM)

#define ZCOL    (HH * CC)          // elements per z column blob = 32768

// W-filtered image, fp16, W-MAJOR layout: z[n][w][h][c].
__device__ __half g_scratch[(size_t)NN * HH * WW * CC];

// ---- R12 pass1: smem copy-in, R7 scan body, w-major z stores ----

// Fwd+bwd IIR (a=b=0.5) over a ROWLEN x CC half2 tile in smem, in place.
// fp32 carry chains in registers; boundary chunks exact w.r.t. reference
// inits (carry = s[0] fwd; carry = s[L-1] = y_f[L-1] bwd).
__device__ __forceinline__ void iir_scan_tile_h2(__half2* s, int tid) {
    const int c     = tid & 31;
    const int chunk = tid >> 5;
    const int w0    = chunk * CLEN;
    const int w1    = w0 + CLEN;

    int ws = w0 - LWARM; if (ws < 0) ws = 0;
    float2 carry = __half22float2(s[ws * H2PW + c]);
    for (int w = ws; w < w0; ++w) {
        const float2 v = __half22float2(s[w * H2PW + c]);
        carry.x = fmaf(0.5f, carry.x, 0.5f * v.x);
        carry.y = fmaf(0.5f, carry.y, 0.5f * v.y);
    }
    __syncthreads();

    #pragma unroll
    for (int w = w0; w < w1; ++w) {
        const float2 v = __half22float2(s[w * H2PW + c]);
        carry.x = fmaf(0.5f, carry.x, 0.5f * v.x);
        carry.y = fmaf(0.5f, carry.y, 0.5f * v.y);
        s[w * H2PW + c] = __floats2half2_rn(carry.x, carry.y);
    }
    __syncthreads();

    int we = w1 - 1 + LWARM; if (we > ROWLEN - 1) we = ROWLEN - 1;
    carry = __half22float2(s[we * H2PW + c]);
    for (int w = we - 1; w >= w1; --w) {
        const float2 v = __half22float2(s[w * H2PW + c]);
        carry.x = fmaf(0.5f, carry.x, 0.5f * v.x);
        carry.y = fmaf(0.5f, carry.y, 0.5f * v.y);
    }
    __syncthreads();

    #pragma unroll
    for (int w = w1 - 1; w >= w0; --w) {
        const float2 v = __half22float2(s[w * H2PW + c]);
        carry.x = fmaf(0.5f, carry.x, 0.5f * v.x);
        carry.y = fmaf(0.5f, carry.y, 0.5f * v.y);
        s[w * H2PW + c] = __floats2half2_rn(carry.x, carry.y);
    }
    __syncthreads();
}

// Pass 1: IIR along W over row (n,h). Reads x (NHWC fp32) into smem,
// scans, writes z in w-major fp16 layout (128B line per w, 64KB stride).
__global__ void __launch_bounds__(THREADS, 3)
pass1_kernel(const float* __restrict__ x) {
    extern __shared__ __half2 s2[];
    uint4* s4 = reinterpret_cast<uint4*>(s2);

    const int    nh    = blockIdx.x;                // n*HH + h
    const int    n     = nh >> 9;
    const int    h     = nh & 511;
    const size_t xbase = (size_t)nh * (WW * CC);
    const size_t zbase = ((size_t)n * WW) * ZCOL + (size_t)h * CC;

    #pragma unroll
    for (int i = threadIdx.x; i < VECH; i += THREADS) {
        const int w = i >> 3;
        const int q = i & 7;
        const float4 a = *(const float4*)(x + xbase + (size_t)w * CC + q * 8);
        const float4 b = *(const float4*)(x + xbase + (size_t)w * CC + q * 8 + 4);
        __half2 hv[4];
        hv[0] = __floats2half2_rn(a.x, a.y);
        hv[1] = __floats2half2_rn(a.z, a.w);
        hv[2] = __floats2half2_rn(b.x, b.y);
        hv[3] = __floats2half2_rn(b.z, b.w);
        s4[w * 8 + q] = *(uint4*)hv;
    }
    __syncthreads();

    iir_scan_tile_h2(s2, threadIdx.x);

    #pragma unroll
    for (int i = threadIdx.x; i < VECH; i += THREADS) {
        const int w = i >> 3;
        const int q = i & 7;
        *(uint4*)(g_scratch + zbase + (size_t)w * ZCOL + q * 8) = s4[w * 8 + q];
    }
}

// ---- R14 pass2: direct-gmem forward scan over the contiguous z blob,
//      smem backward, inverse-stencil epilogue (never reads fp32 x) ----
__global__ void __launch_bounds__(THREADS, 3)
pass2_kernel(const float* __restrict__ alpha,
             float*       __restrict__ out) {
    extern __shared__ __half2 s2[];
    __shared__ __align__(16) float sm[CPB];

    const int    nw    = blockIdx.x;                // n*WW + w
    const int    n     = nw >> 9;
    const int    w     = nw & 511;
    const size_t zbase = ((size_t)n * WW + w) * ZCOL;
    const size_t obase = (size_t)n * (HH * WW * CC) + (size_t)w * CC;
    const __half* z0   = g_scratch + zbase;

    if (threadIdx.x < CPB)
        sm[threadIdx.x] = 1.0f / (1.0f + expf(-alpha[threadIdx.x]));

    const int c2    = threadIdx.x & 31;
    const int chunk = threadIdx.x >> 5;
    const int h0    = chunk * CLEN;
    const int h1    = h0 + CLEN;

    // ---- forward warm-up: gmem fp16 reads from the z blob ----
    int hs = h0 - LWARM; if (hs < 0) hs = 0;
    float2 carry = __half22float2(*(const __half2*)(z0 + (size_t)hs * CC + c2 * 2));
    for (int h = hs; h < h0; ++h) {
        const float2 v = __half22float2(*(const __half2*)(z0 + (size_t)h * CC + c2 * 2));
        carry.x = fmaf(0.5f, carry.x, 0.5f * v.x);
        carry.y = fmaf(0.5f, carry.y, 0.5f * v.y);
    }
    // No barrier: smem untouched so far (sm[] written pre-scan, read post-sync).

    // ---- forward scan: gmem fp16 in, smem fp16 y_f out ----
    #pragma unroll 8
    for (int h = h0; h < h1; ++h) {
        const float2 v = __half22float2(*(const __half2*)(z0 + (size_t)h * CC + c2 * 2));
        carry.x = fmaf(0.5f, carry.x, 0.5f * v.x);
        carry.y = fmaf(0.5f, carry.y, 0.5f * v.y);
        s2[h * H2PW + c2] = __floats2half2_rn(carry.x, carry.y);
    }
    __syncthreads();

    // ---- backward warm-up (smem y_f) ----
    int he = h1 - 1 + LWARM; if (he > ROWLEN - 1) he = ROWLEN - 1;
    carry = __half22float2(s2[he * H2PW + c2]);
    for (int h = he - 1; h >= h1; --h) {
        const float2 v = __half22float2(s2[h * H2PW + c2]);
        carry.x = fmaf(0.5f, carry.x, 0.5f * v.x);
        carry.y = fmaf(0.5f, carry.y, 0.5f * v.y);
    }
    __syncthreads();

    // ---- backward scan, in place ----
    #pragma unroll
    for (int h = h1 - 1; h >= h0; --h) {
        const float2 v = __half22float2(s2[h * H2PW + c2]);
        carry.x = fmaf(0.5f, carry.x, 0.5f * v.x);
        carry.y = fmaf(0.5f, carry.y, 0.5f * v.y);
        s2[h * H2PW + c2] = __floats2half2_rn(carry.x, carry.y);
    }
    __syncthreads();

    // Exact inverse of the W filter:
    //   w in [1,510]: x = 5 z[w] - 2 z[w-1] - 2 z[w+1]
    //   w = 0:        x = 2 z[0] - z[1]
    //   w = 511:      x = 3 z[511] - 2 z[510]
    float cm, c0, cp;
    const __half *zm, *zp;
    if (w == 0)        { cm = 0.f;  c0 = 2.f; cp = -1.f;
                         zm = z0;          zp = z0 + ZCOL; }
    else if (w == 511) { cm = -2.f; c0 = 3.f; cp = 0.f;
                         zm = z0 - ZCOL;   zp = z0; }
    else               { cm = -2.f; c0 = 5.f; cp = -2.f;
                         zm = z0 - ZCOL;   zp = z0 + ZCOL; }

    // Epilogue: per i -> (h, q) = 8 channels; 3x 16B z (L2-hot) + 16B y
    // (smem) in, 32B out. Independent iterations, full MLP.
    #pragma unroll
    for (int i = threadIdx.x; i < VECH; i += THREADS) {
        const int    h  = i >> 3;
        const int    q  = i & 7;
        const size_t zo = (size_t)h * CC + q * 8;
        const uint4  u0 = *(const uint4*)(z0 + zo);
        const uint4  um = *(const uint4*)(zm + zo);
        const uint4  up = *(const uint4*)(zp + zo);
        const __half2* hz0 = (const __half2*)&u0;
        const __half2* hzm = (const __half2*)&um;
        const __half2* hzp = (const __half2*)&up;
        const __half2* hy  = s2 + h * H2PW + q * 4;

        float outv[8];
        #pragma unroll
        for (int k = 0; k < 4; ++k) {
            const float2 v0 = __half22float2(hz0[k]);
            const float2 vm = __half22float2(hzm[k]);
            const float2 vp = __half22float2(hzp[k]);
            const float2 yv = __half22float2(hy[k]);
            const float2 mv = *(const float2*)(&sm[q * 8 + k * 2]);
            float xr, xi;
            xr = fmaf(c0, v0.x, fmaf(cm, vm.x, cp * vp.x));
            xi = fmaf(c0, v0.y, fmaf(cm, vm.y, cp * vp.y));
            outv[2 * k]     = fmaf(mv.x, yv.x - xr, xr);
            outv[2 * k + 1] = fmaf(mv.y, yv.y - xi, xi);
        }
        float* op = out + obase + (size_t)h * (WW * CC) + q * 8;
        *(float4*)op       = *(float4*)&outv[0];
        *(float4*)(op + 4) = *(float4*)&outv[4];
    }
}

extern "C" void kernel_launch(void* const* d_in, const int* in_sizes, int n_in,
                              void* d_out, int out_size) {
    const float* x     = (const float*)d_in[0];
    const float* alpha = (const float*)d_in[1];
    float*       out   = (float*)d_out;

    // >48KB dynamic smem opt-in (idempotent, capture-safe).
    cudaFuncSetAttribute(pass1_kernel,
                         cudaFuncAttributeMaxDynamicSharedMemorySize, SMEM_BYTES);
    cudaFuncSetAttribute(pass2_kernel,
                         cudaFuncAttributeMaxDynamicSharedMemorySize, SMEM_BYTES);

    pass1_kernel<<<NN * HH, THREADS, SMEM_BYTES>>>(x);
    pass2_kernel<<<NN * WW, THREADS, SMEM_BYTES>>>(alpha, out);
}